// round 7
// baseline (speedup 1.0000x reference)
#include <cuda_runtime.h>
#include <cstdint>
#include <mma.h>
#include <math.h>

using namespace nvcuda;

// ---------------------------------------------------------------------------
// Problem constants
// ---------------------------------------------------------------------------
#define NODES0 200000
#define NODES1 100000
#define NODES2 50000
#define NODES3 25000
#define FIN    256
#define DH     64
#define NHEAD  3
#define COUT   40
#define FMID   (NHEAD * DH)   // 192
#define COUT_PAD 48
#define EDGE_MAX 1000000

// ---------------------------------------------------------------------------
// Static device scratch
// ---------------------------------------------------------------------------
__device__ __align__(128) float g_hbuf[(size_t)NODES0 * FMID];
__device__ __align__(128) float g_obuf[(size_t)NODES1 * FMID];
__device__ __align__(128) float g_el[(size_t)NODES0 * NHEAD];
__device__ __align__(128) float g_er[(size_t)NODES0 * NHEAD];
__device__ __align__(128) float g_alpha[(size_t)EDGE_MAX * NHEAD];
__device__ __align__(128) float g_W0r[FIN * FMID];
__device__ __align__(128) float g_W1r[FMID * FMID];
__device__ __align__(128) float g_W2r[FMID * COUT];
__device__ int g_rowptr[NODES1 + 1];

// ---------------------------------------------------------------------------
// cp.async helpers
// ---------------------------------------------------------------------------
__device__ __forceinline__ unsigned int smem_u32(const void* p) {
    return (unsigned int)__cvta_generic_to_shared(p);
}
__device__ __forceinline__ void cp16(unsigned int d, const void* s) {
    asm volatile("cp.async.cg.shared.global [%0], [%1], 16;" :: "r"(d), "l"(s));
}
#define CP_COMMIT() asm volatile("cp.async.commit_group;")
#define CP_WAIT1()  asm volatile("cp.async.wait_group 1;")

// ---------------------------------------------------------------------------
// Pre-round weight matrices to tf32-representable fp32 (RN), once per call.
// ---------------------------------------------------------------------------
__global__ void round_w_kernel(const float* __restrict__ W0,
                               const float* __restrict__ W1,
                               const float* __restrict__ W2,
                               float* __restrict__ W0r,
                               float* __restrict__ W1r,
                               float* __restrict__ W2r)
{
    int i = blockIdx.x * blockDim.x + threadIdx.x;
    if (i < FIN * FMID)  W0r[i] = wmma::__float_to_tf32(W0[i]);
    if (i < FMID * FMID) W1r[i] = wmma::__float_to_tf32(W1[i]);
    if (i < FMID * COUT) W2r[i] = wmma::__float_to_tf32(W2[i]);
}

// ---------------------------------------------------------------------------
// TF32 wmma GEMM, 3-stage cp.async pipeline, FUSED el/er epilogue.
// Structural invariant exploited: with BN=64 and D=64, each block's column
// range is exactly one attention head (head = bcol/64; layer 2's single
// column block is head 0). After storing C, the block re-reads its own
// (L1/L2-hot) tile and computes el[row,head], er[row,head] directly —
// no atomics, no separate elr pass over DRAM.
// ---------------------------------------------------------------------------
template <bool CONVA>
__global__ __launch_bounds__(256) void gemm_tf32_pipe(
    const float* __restrict__ A, const float* __restrict__ B,
    float* C, int M, int N, int K, int ldc,
    const float* __restrict__ alv, const float* __restrict__ arv,
    float* __restrict__ el, float* __restrict__ er, int H)
{
    constexpr int BM = 128, BN = 64, BK = 16;
    constexpr int LDA = BK + 4;   // 20
    constexpr int LDB = BN + 4;   // 68

    __shared__ float As[3][BM * LDA];
    __shared__ float Bs[3][BK * LDB];

    const int tid  = threadIdx.x;
    const int warp = tid >> 5;
    const int wm   = warp >> 1;
    const int wn   = warp & 1;
    const int brow = blockIdx.y * BM;
    const int bcol = blockIdx.x * BN;
    const int T    = K / BK;

    wmma::fragment<wmma::accumulator, 16, 16, 8, float> acc[2][2];
#pragma unroll
    for (int i = 0; i < 2; i++)
#pragma unroll
        for (int j = 0; j < 2; j++) wmma::fill_fragment(acc[i][j], 0.0f);

    const int br  = tid >> 4;
    const int bc4 = tid & 15;
    int bgcol = bcol + bc4 * 4;
    if (bgcol + 4 > N) bgcol = N - 4;   // clamp; garbage lands only in
                                        // padded output cols, excluded below

#define PREFETCH(t, st)                                                        \
    do {                                                                       \
        int k0 = (t) * BK;                                                     \
        _Pragma("unroll")                                                      \
        for (int i = 0; i < 2; i++) {                                          \
            int idx = tid + i * 256;                                           \
            int r   = idx >> 2;                                                \
            int c4  = idx & 3;                                                 \
            int grow = brow + r;                                               \
            if (grow >= M) grow = M - 1;                                       \
            cp16(smem_u32(&As[st][r * LDA + c4 * 4]),                          \
                 &A[(size_t)grow * K + k0 + c4 * 4]);                          \
        }                                                                      \
        cp16(smem_u32(&Bs[st][br * LDB + bc4 * 4]),                            \
             &B[(size_t)(k0 + br) * N + bgcol]);                               \
        CP_COMMIT();                                                           \
    } while (0)

    PREFETCH(0, 0);
    PREFETCH(1, 1);

    for (int t = 0; t < T; t++) {
        CP_WAIT1();
        __syncthreads();
        if (t + 2 < T) {
            int st2 = (t + 2) % 3;
            PREFETCH(t + 2, st2);
        } else {
            CP_COMMIT();
        }
        const int st = t % 3;
#pragma unroll
        for (int kk = 0; kk < BK; kk += 8) {
            wmma::fragment<wmma::matrix_a, 16, 16, 8, wmma::precision::tf32, wmma::row_major> a[2];
            wmma::fragment<wmma::matrix_b, 16, 16, 8, wmma::precision::tf32, wmma::row_major> b[2];
#pragma unroll
            for (int i = 0; i < 2; i++) {
                wmma::load_matrix_sync(a[i], &As[st][(wm * 32 + i * 16) * LDA + kk], LDA);
                if (CONVA) {
#pragma unroll
                    for (int e = 0; e < a[i].num_elements; e++)
                        a[i].x[e] = wmma::__float_to_tf32(a[i].x[e]);
                }
            }
#pragma unroll
            for (int j = 0; j < 2; j++)
                wmma::load_matrix_sync(b[j], &Bs[st][kk * LDB + wn * 32 + j * 16], LDB);
#pragma unroll
            for (int i = 0; i < 2; i++)
#pragma unroll
                for (int j = 0; j < 2; j++)
                    wmma::mma_sync(acc[i][j], a[i], b[j], acc[i][j]);
        }
    }
#undef PREFETCH

#pragma unroll
    for (int i = 0; i < 2; i++) {
        int row0 = brow + wm * 32 + i * 16;
        if (row0 + 16 > M) continue;
#pragma unroll
        for (int j = 0; j < 2; j++) {
            int col0 = bcol + wn * 32 + j * 16;
            if (col0 + 16 > ldc) continue;
            wmma::store_matrix_sync(&C[(size_t)row0 * ldc + col0], acc[i][j], ldc,
                                    wmma::mem_row_major);
        }
    }

    // ---- Fused el/er epilogue ----
    __syncthreads();   // all C-tile stores issued
    {
        const int r    = tid >> 1;       // 0..127
        const int half = tid & 1;        // 0/1
        const int row  = brow + r;
        float sl = 0.f, sr = 0.f;
        if (row < M) {
            const int cbase = bcol + half * 32;
            const float* crow = C + (size_t)row * ldc;
#pragma unroll 8
            for (int c = 0; c < 32; c++) {
                int col = cbase + c;
                if (col < N) {
                    float v = crow[col];
                    sl = fmaf(v, alv[col], sl);
                    sr = fmaf(v, arv[col], sr);
                }
            }
        }
        sl += __shfl_xor_sync(0xffffffffu, sl, 1);
        sr += __shfl_xor_sync(0xffffffffu, sr, 1);
        if (half == 0 && row < M) {
            const int head = bcol >> 6;   // D=64 layers; layer 2: bcol=0
            el[row * H + head] = sl;
            er[row * H + head] = sr;
        }
    }
}

// ---------------------------------------------------------------------------
// row_ptr from sorted dst — edge-diff scatter (thread per edge).
// rp[d] = first index e with dst[e] >= d.
// ---------------------------------------------------------------------------
__global__ void rowptr_fast(const int* __restrict__ dst, int E, int n_dst,
                            int* __restrict__ rp)
{
    int e = blockIdx.x * blockDim.x + threadIdx.x;
    if (e >= E) return;
    int d1 = dst[e];
    int d0 = (e == 0) ? -1 : dst[e - 1];
    for (int d = d0 + 1; d <= d1; d++) rp[d] = e;
    if (e == E - 1)
        for (int d = d1 + 1; d <= n_dst; d++) rp[d] = E;
}

// ---------------------------------------------------------------------------
// gat_softmax: warp per dst. Max-shifted softmax; writes normalized alpha.
// ---------------------------------------------------------------------------
__device__ __forceinline__ float leaky02(float v) {
    return v > 0.f ? v : 0.2f * v;
}

template <int H>
__global__ __launch_bounds__(256) void gat_softmax(
    const float* __restrict__ el, const float* __restrict__ er,
    const int* __restrict__ src, const int* __restrict__ rp,
    float* __restrict__ alpha, int n_dst)
{
    const int gw = (blockIdx.x * blockDim.x + threadIdx.x) >> 5;
    if (gw >= n_dst) return;
    const int lane = threadIdx.x & 31;
    const int d = gw;
    const int start = rp[d];
    const int end   = rp[d + 1];

    float er_d[H];
#pragma unroll
    for (int hh = 0; hh < H; hh++) er_d[hh] = er[d * H + hh];

    float v0[H], m[H];
#pragma unroll
    for (int hh = 0; hh < H; hh++) { v0[hh] = 0.f; m[hh] = -INFINITY; }
    {
        int e = start + lane;
        if (e < end) {
            int sn = src[e];
#pragma unroll
            for (int hh = 0; hh < H; hh++) {
                v0[hh] = leaky02(el[sn * H + hh] + er_d[hh]);
                m[hh]  = v0[hh];
            }
        }
    }
    for (int e = start + 32 + lane; e < end; e += 32) {
        int sn = src[e];
#pragma unroll
        for (int hh = 0; hh < H; hh++)
            m[hh] = fmaxf(m[hh], leaky02(el[sn * H + hh] + er_d[hh]));
    }
#pragma unroll
    for (int hh = 0; hh < H; hh++)
#pragma unroll
        for (int o = 16; o; o >>= 1)
            m[hh] = fmaxf(m[hh], __shfl_xor_sync(0xffffffffu, m[hh], o));

    float w0[H], s[H];
#pragma unroll
    for (int hh = 0; hh < H; hh++) { s[hh] = 0.f; w0[hh] = 0.f; }
    if (start + lane < end) {
#pragma unroll
        for (int hh = 0; hh < H; hh++) {
            w0[hh] = __expf(v0[hh] - m[hh]);
            s[hh]  = w0[hh];
        }
    }
    for (int e = start + 32 + lane; e < end; e += 32) {
        int sn = src[e];
#pragma unroll
        for (int hh = 0; hh < H; hh++)
            s[hh] += __expf(leaky02(el[sn * H + hh] + er_d[hh]) - m[hh]);
    }
#pragma unroll
    for (int hh = 0; hh < H; hh++)
#pragma unroll
        for (int o = 16; o; o >>= 1)
            s[hh] += __shfl_xor_sync(0xffffffffu, s[hh], o);
    float inv[H];
#pragma unroll
    for (int hh = 0; hh < H; hh++)
        inv[hh] = (s[hh] > 0.f) ? 1.0f / s[hh] : 0.f;

    if (start + lane < end) {
        int e = start + lane;
#pragma unroll
        for (int hh = 0; hh < H; hh++)
            alpha[(size_t)e * H + hh] = w0[hh] * inv[hh];
    }
    for (int e = start + 32 + lane; e < end; e += 32) {
        int sn = src[e];
#pragma unroll
        for (int hh = 0; hh < H; hh++)
            alpha[(size_t)e * H + hh] =
                __expf(leaky02(el[sn * H + hh] + er_d[hh]) - m[hh]) * inv[hh];
    }
}

// ---------------------------------------------------------------------------
// gat_gather: warp per dst. Pure weighted feature gather, unrolled by 2.
// ---------------------------------------------------------------------------
template <int H, int D, int STRIDE, bool RELU, bool TF32OUT>
__global__ __launch_bounds__(256) void gat_gather(
    const float* __restrict__ h, const float* __restrict__ alpha,
    const int* __restrict__ src, const int* __restrict__ rp,
    float* __restrict__ out, int n_dst)
{
    constexpr int HD  = H * D;
    constexpr int HD4 = HD / 4;
    constexpr int NJ  = (HD4 + 31) / 32;

    const int gw = (blockIdx.x * blockDim.x + threadIdx.x) >> 5;
    if (gw >= n_dst) return;
    const int lane = threadIdx.x & 31;
    const int d = gw;
    const int start = rp[d];
    const int end   = rp[d + 1];

    int headj[NJ];
#pragma unroll
    for (int jj = 0; jj < NJ; jj++) {
        int j = lane + jj * 32;
        int hh = (j * 4) / D;
        headj[jj] = hh < H ? hh : H - 1;
    }

    float4 facc[NJ];
#pragma unroll
    for (int jj = 0; jj < NJ; jj++) facc[jj] = make_float4(0.f, 0.f, 0.f, 0.f);

    int e = start;
    for (; e + 2 <= end; e += 2) {
        const int sn0 = __ldg(&src[e]);
        const int sn1 = __ldg(&src[e + 1]);
        float a0[NJ], a1[NJ];
#pragma unroll
        for (int jj = 0; jj < NJ; jj++) {
            a0[jj] = __ldg(&alpha[(size_t)e * H + headj[jj]]);
            a1[jj] = __ldg(&alpha[(size_t)(e + 1) * H + headj[jj]]);
        }
        const float4* hp0 = (const float4*)(h + (size_t)sn0 * STRIDE);
        const float4* hp1 = (const float4*)(h + (size_t)sn1 * STRIDE);
#pragma unroll
        for (int jj = 0; jj < NJ; jj++) {
            int j = lane + jj * 32;
            if (j < HD4) {
                float4 v0 = hp0[j];
                float4 v1 = hp1[j];
                facc[jj].x = fmaf(v0.x, a0[jj], facc[jj].x);
                facc[jj].y = fmaf(v0.y, a0[jj], facc[jj].y);
                facc[jj].z = fmaf(v0.z, a0[jj], facc[jj].z);
                facc[jj].w = fmaf(v0.w, a0[jj], facc[jj].w);
                facc[jj].x = fmaf(v1.x, a1[jj], facc[jj].x);
                facc[jj].y = fmaf(v1.y, a1[jj], facc[jj].y);
                facc[jj].z = fmaf(v1.z, a1[jj], facc[jj].z);
                facc[jj].w = fmaf(v1.w, a1[jj], facc[jj].w);
            }
        }
    }
    if (e < end) {
        const int sn0 = __ldg(&src[e]);
        const float4* hp0 = (const float4*)(h + (size_t)sn0 * STRIDE);
#pragma unroll
        for (int jj = 0; jj < NJ; jj++) {
            int j = lane + jj * 32;
            if (j < HD4) {
                float a = __ldg(&alpha[(size_t)e * H + headj[jj]]);
                float4 v = hp0[j];
                facc[jj].x = fmaf(v.x, a, facc[jj].x);
                facc[jj].y = fmaf(v.y, a, facc[jj].y);
                facc[jj].z = fmaf(v.z, a, facc[jj].z);
                facc[jj].w = fmaf(v.w, a, facc[jj].w);
            }
        }
    }

#pragma unroll
    for (int jj = 0; jj < NJ; jj++) {
        int j = lane + jj * 32;
        if (j < HD4) {
            float4 r = facc[jj];
            if (RELU) {
                r.x = fmaxf(r.x, 0.f); r.y = fmaxf(r.y, 0.f);
                r.z = fmaxf(r.z, 0.f); r.w = fmaxf(r.w, 0.f);
            }
            if (TF32OUT) {
                r.x = wmma::__float_to_tf32(r.x);
                r.y = wmma::__float_to_tf32(r.y);
                r.z = wmma::__float_to_tf32(r.z);
                r.w = wmma::__float_to_tf32(r.w);
            }
            ((float4*)(out + (size_t)d * HD))[j] = r;
        }
    }
}

// ---------------------------------------------------------------------------
// Launch
// ---------------------------------------------------------------------------
static inline int ceil_div(int a, int b) { return (a + b - 1) / b; }

extern "C" void kernel_launch(void* const* d_in, const int* in_sizes, int n_in,
                              void* d_out, int out_size)
{
    const float* x    = (const float*)d_in[0];
    const int*   src0 = (const int*)  d_in[1];
    const int*   dst0 = (const int*)  d_in[2];
    const int*   src1 = (const int*)  d_in[3];
    const int*   dst1 = (const int*)  d_in[4];
    const int*   src2 = (const int*)  d_in[5];
    const int*   dst2 = (const int*)  d_in[6];
    const float* W0   = (const float*)d_in[7];
    const float* al0  = (const float*)d_in[8];
    const float* ar0  = (const float*)d_in[9];
    const float* W1   = (const float*)d_in[10];
    const float* al1  = (const float*)d_in[11];
    const float* ar1  = (const float*)d_in[12];
    const float* W2   = (const float*)d_in[13];
    const float* al2  = (const float*)d_in[14];
    const float* ar2  = (const float*)d_in[15];
    float* out = (float*)d_out;

    const int E0 = in_sizes[1];
    const int E1 = in_sizes[3];
    const int E2 = in_sizes[5];

    float *hbuf, *obuf, *el, *er, *alpha, *w0r, *w1r, *w2r;
    int* rp;
    cudaGetSymbolAddress((void**)&hbuf,  g_hbuf);
    cudaGetSymbolAddress((void**)&obuf,  g_obuf);
    cudaGetSymbolAddress((void**)&el,    g_el);
    cudaGetSymbolAddress((void**)&er,    g_er);
    cudaGetSymbolAddress((void**)&alpha, g_alpha);
    cudaGetSymbolAddress((void**)&w0r,   g_W0r);
    cudaGetSymbolAddress((void**)&w1r,   g_W1r);
    cudaGetSymbolAddress((void**)&w2r,   g_W2r);
    cudaGetSymbolAddress((void**)&rp,    g_rowptr);

    round_w_kernel<<<ceil_div(FIN * FMID, 256), 256>>>(W0, W1, W2, w0r, w1r, w2r);

    // ---------------- Layer 0: 200000x256 @ 256x192 ----------------
    {
        dim3 grid(FMID / 64, ceil_div(NODES0, 128));
        gemm_tf32_pipe<true><<<grid, 256>>>(x, w0r, hbuf, NODES0, FMID, FIN, FMID,
                                            al0, ar0, el, er, NHEAD);
        rowptr_fast<<<ceil_div(E0, 256), 256>>>(dst0, E0, NODES1, rp);
        gat_softmax<NHEAD><<<ceil_div(NODES1, 8), 256>>>(el, er, src0, rp, alpha, NODES1);
        gat_gather<NHEAD, DH, FMID, true, true><<<ceil_div(NODES1, 8), 256>>>(
            hbuf, alpha, src0, rp, obuf, NODES1);
    }

    // ---------------- Layer 1: 100000x192 @ 192x192 ----------------
    {
        dim3 grid(FMID / 64, ceil_div(NODES1, 128));
        gemm_tf32_pipe<false><<<grid, 256>>>(obuf, w1r, hbuf, NODES1, FMID, FMID, FMID,
                                             al1, ar1, el, er, NHEAD);
        rowptr_fast<<<ceil_div(E1, 256), 256>>>(dst1, E1, NODES2, rp);
        gat_softmax<NHEAD><<<ceil_div(NODES2, 8), 256>>>(el, er, src1, rp, alpha, NODES2);
        gat_gather<NHEAD, DH, FMID, true, true><<<ceil_div(NODES2, 8), 256>>>(
            hbuf, alpha, src1, rp, obuf, NODES2);
    }

    // ---------------- Layer 2: 50000x192 @ 192x40 (padded ldc=48) -------
    {
        dim3 grid(1, ceil_div(NODES2, 128));
        gemm_tf32_pipe<false><<<grid, 256>>>(obuf, w2r, hbuf, NODES2, COUT, FMID, COUT_PAD,
                                             al2, ar2, el, er, 1);
        rowptr_fast<<<ceil_div(E2, 256), 256>>>(dst2, E2, NODES3, rp);
        gat_softmax<1><<<ceil_div(NODES3, 8), 256>>>(el, er, src2, rp, alpha, NODES3);
        gat_gather<1, COUT, COUT_PAD, false, false><<<ceil_div(NODES3, 8), 256>>>(
            hbuf, alpha, src2, rp, out, NODES3);
    }
}

// round 8
// speedup vs baseline: 1.0576x; 1.0576x over previous
#include <cuda_runtime.h>
#include <cstdint>
#include <mma.h>
#include <math.h>

using namespace nvcuda;

// ---------------------------------------------------------------------------
// Problem constants
// ---------------------------------------------------------------------------
#define NODES0 200000
#define NODES1 100000
#define NODES2 50000
#define NODES3 25000
#define FIN    256
#define DH     64
#define NHEAD  3
#define COUT   40
#define FMID   (NHEAD * DH)   // 192
#define COUT_PAD 48
#define EDGE_MAX 1000000

// ---------------------------------------------------------------------------
// Static device scratch
// ---------------------------------------------------------------------------
__device__ __align__(128) float g_hbuf[(size_t)NODES0 * FMID];
__device__ __align__(128) float g_obuf[(size_t)NODES1 * FMID];
__device__ __align__(128) float g_el[(size_t)NODES0 * NHEAD];
__device__ __align__(128) float g_er[(size_t)NODES0 * NHEAD];
__device__ __align__(128) float g_alpha[(size_t)EDGE_MAX * NHEAD];
__device__ __align__(128) float g_W0r[FIN * FMID];
__device__ __align__(128) float g_W1r[FMID * FMID];
__device__ __align__(128) float g_W2r[FMID * COUT];
__device__ int g_rowptr[NODES1 + 1];

// ---------------------------------------------------------------------------
// cp.async helpers
// ---------------------------------------------------------------------------
__device__ __forceinline__ unsigned int smem_u32(const void* p) {
    return (unsigned int)__cvta_generic_to_shared(p);
}
__device__ __forceinline__ void cp16(unsigned int d, const void* s) {
    asm volatile("cp.async.cg.shared.global [%0], [%1], 16;" :: "r"(d), "l"(s));
}
#define CP_COMMIT() asm volatile("cp.async.commit_group;")
#define CP_WAIT1()  asm volatile("cp.async.wait_group 1;")

// ---------------------------------------------------------------------------
// Pre-round weight matrices to tf32-representable fp32 (RN), once per call.
// ---------------------------------------------------------------------------
__global__ void round_w_kernel(const float* __restrict__ W0,
                               const float* __restrict__ W1,
                               const float* __restrict__ W2,
                               float* __restrict__ W0r,
                               float* __restrict__ W1r,
                               float* __restrict__ W2r)
{
    int i = blockIdx.x * blockDim.x + threadIdx.x;
    if (i < FIN * FMID)  W0r[i] = wmma::__float_to_tf32(W0[i]);
    if (i < FMID * FMID) W1r[i] = wmma::__float_to_tf32(W1[i]);
    if (i < FMID * COUT) W2r[i] = wmma::__float_to_tf32(W2[i]);
}

// ---------------------------------------------------------------------------
// TF32 wmma GEMM, 3-stage cp.async pipeline (R6-proven config, NO epilogue).
// ---------------------------------------------------------------------------
template <bool CONVA>
__global__ __launch_bounds__(256) void gemm_tf32_pipe(
    const float* __restrict__ A, const float* __restrict__ B,
    float* __restrict__ C, int M, int N, int K, int ldc)
{
    constexpr int BM = 128, BN = 64, BK = 16;
    constexpr int LDA = BK + 4;   // 20
    constexpr int LDB = BN + 4;   // 68

    __shared__ float As[3][BM * LDA];
    __shared__ float Bs[3][BK * LDB];

    const int tid  = threadIdx.x;
    const int warp = tid >> 5;
    const int wm   = warp >> 1;
    const int wn   = warp & 1;
    const int brow = blockIdx.y * BM;
    const int bcol = blockIdx.x * BN;
    const int T    = K / BK;

    wmma::fragment<wmma::accumulator, 16, 16, 8, float> acc[2][2];
#pragma unroll
    for (int i = 0; i < 2; i++)
#pragma unroll
        for (int j = 0; j < 2; j++) wmma::fill_fragment(acc[i][j], 0.0f);

    const int br  = tid >> 4;
    const int bc4 = tid & 15;
    int bgcol = bcol + bc4 * 4;
    if (bgcol + 4 > N) bgcol = N - 4;   // clamp; garbage lands only in
                                        // padded output cols, never read

#define PREFETCH(t, st)                                                        \
    do {                                                                       \
        int k0 = (t) * BK;                                                     \
        _Pragma("unroll")                                                      \
        for (int i = 0; i < 2; i++) {                                          \
            int idx = tid + i * 256;                                           \
            int r   = idx >> 2;                                                \
            int c4  = idx & 3;                                                 \
            int grow = brow + r;                                               \
            if (grow >= M) grow = M - 1;                                       \
            cp16(smem_u32(&As[st][r * LDA + c4 * 4]),                          \
                 &A[(size_t)grow * K + k0 + c4 * 4]);                          \
        }                                                                      \
        cp16(smem_u32(&Bs[st][br * LDB + bc4 * 4]),                            \
             &B[(size_t)(k0 + br) * N + bgcol]);                               \
        CP_COMMIT();                                                           \
    } while (0)

    PREFETCH(0, 0);
    PREFETCH(1, 1);

    for (int t = 0; t < T; t++) {
        CP_WAIT1();
        __syncthreads();
        if (t + 2 < T) {
            int st2 = (t + 2) % 3;
            PREFETCH(t + 2, st2);
        } else {
            CP_COMMIT();
        }
        const int st = t % 3;
#pragma unroll
        for (int kk = 0; kk < BK; kk += 8) {
            wmma::fragment<wmma::matrix_a, 16, 16, 8, wmma::precision::tf32, wmma::row_major> a[2];
            wmma::fragment<wmma::matrix_b, 16, 16, 8, wmma::precision::tf32, wmma::row_major> b[2];
#pragma unroll
            for (int i = 0; i < 2; i++) {
                wmma::load_matrix_sync(a[i], &As[st][(wm * 32 + i * 16) * LDA + kk], LDA);
                if (CONVA) {
#pragma unroll
                    for (int e = 0; e < a[i].num_elements; e++)
                        a[i].x[e] = wmma::__float_to_tf32(a[i].x[e]);
                }
            }
#pragma unroll
            for (int j = 0; j < 2; j++)
                wmma::load_matrix_sync(b[j], &Bs[st][kk * LDB + wn * 32 + j * 16], LDB);
#pragma unroll
            for (int i = 0; i < 2; i++)
#pragma unroll
                for (int j = 0; j < 2; j++)
                    wmma::mma_sync(acc[i][j], a[i], b[j], acc[i][j]);
        }
    }
#undef PREFETCH

#pragma unroll
    for (int i = 0; i < 2; i++) {
        int row0 = brow + wm * 32 + i * 16;
        if (row0 + 16 > M) continue;
#pragma unroll
        for (int j = 0; j < 2; j++) {
            int col0 = bcol + wn * 32 + j * 16;
            if (col0 + 16 > ldc) continue;
            wmma::store_matrix_sync(&C[(size_t)row0 * ldc + col0], acc[i][j], ldc,
                                    wmma::mem_row_major);
        }
    }
}

// ---------------------------------------------------------------------------
// Per-node attention logits, float4-vectorized. One warp per (node, head).
// ---------------------------------------------------------------------------
__global__ void elr_kernel(const float* __restrict__ h,
                           const float* __restrict__ al,
                           const float* __restrict__ ar,
                           float* __restrict__ el, float* __restrict__ er,
                           int Nn, int H, int D, int stride)
{
    int gw   = (blockIdx.x * blockDim.x + threadIdx.x) >> 5;
    int lane = threadIdx.x & 31;
    if (gw >= Nn * H) return;
    int n = gw / H, head = gw % H;
    const float4* hp  = (const float4*)(h + (size_t)n * stride + head * D);
    const float4* alp = (const float4*)(al + head * D);
    const float4* arp = (const float4*)(ar + head * D);
    const int nd4 = D >> 2;            // 16 (D=64) or 10 (D=40)
    float sl = 0.f, sr = 0.f;
    for (int i = lane; i < nd4; i += 32) {
        float4 v = hp[i];
        float4 a = alp[i];
        float4 b = arp[i];
        sl = fmaf(v.x, a.x, fmaf(v.y, a.y, fmaf(v.z, a.z, fmaf(v.w, a.w, sl))));
        sr = fmaf(v.x, b.x, fmaf(v.y, b.y, fmaf(v.z, b.z, fmaf(v.w, b.w, sr))));
    }
#pragma unroll
    for (int o = 16; o; o >>= 1) {
        sl += __shfl_xor_sync(0xffffffffu, sl, o);
        sr += __shfl_xor_sync(0xffffffffu, sr, o);
    }
    if (lane == 0) {
        el[n * H + head] = sl;
        er[n * H + head] = sr;
    }
}

// ---------------------------------------------------------------------------
// row_ptr from sorted dst — edge-diff scatter (thread per edge).
// ---------------------------------------------------------------------------
__global__ void rowptr_fast(const int* __restrict__ dst, int E, int n_dst,
                            int* __restrict__ rp)
{
    int e = blockIdx.x * blockDim.x + threadIdx.x;
    if (e >= E) return;
    int d1 = dst[e];
    int d0 = (e == 0) ? -1 : dst[e - 1];
    for (int d = d0 + 1; d <= d1; d++) rp[d] = e;
    if (e == E - 1)
        for (int d = d1 + 1; d <= n_dst; d++) rp[d] = E;
}

// ---------------------------------------------------------------------------
// gat_softmax: warp per dst. Max-shifted softmax; writes normalized alpha.
// ---------------------------------------------------------------------------
__device__ __forceinline__ float leaky02(float v) {
    return v > 0.f ? v : 0.2f * v;
}

template <int H>
__global__ __launch_bounds__(256) void gat_softmax(
    const float* __restrict__ el, const float* __restrict__ er,
    const int* __restrict__ src, const int* __restrict__ rp,
    float* __restrict__ alpha, int n_dst)
{
    const int gw = (blockIdx.x * blockDim.x + threadIdx.x) >> 5;
    if (gw >= n_dst) return;
    const int lane = threadIdx.x & 31;
    const int d = gw;
    const int start = rp[d];
    const int end   = rp[d + 1];

    float er_d[H];
#pragma unroll
    for (int hh = 0; hh < H; hh++) er_d[hh] = er[d * H + hh];

    float v0[H], m[H];
#pragma unroll
    for (int hh = 0; hh < H; hh++) { v0[hh] = 0.f; m[hh] = -INFINITY; }
    {
        int e = start + lane;
        if (e < end) {
            int sn = src[e];
#pragma unroll
            for (int hh = 0; hh < H; hh++) {
                v0[hh] = leaky02(el[sn * H + hh] + er_d[hh]);
                m[hh]  = v0[hh];
            }
        }
    }
    for (int e = start + 32 + lane; e < end; e += 32) {
        int sn = src[e];
#pragma unroll
        for (int hh = 0; hh < H; hh++)
            m[hh] = fmaxf(m[hh], leaky02(el[sn * H + hh] + er_d[hh]));
    }
#pragma unroll
    for (int hh = 0; hh < H; hh++)
#pragma unroll
        for (int o = 16; o; o >>= 1)
            m[hh] = fmaxf(m[hh], __shfl_xor_sync(0xffffffffu, m[hh], o));

    float w0[H], s[H];
#pragma unroll
    for (int hh = 0; hh < H; hh++) { s[hh] = 0.f; w0[hh] = 0.f; }
    if (start + lane < end) {
#pragma unroll
        for (int hh = 0; hh < H; hh++) {
            w0[hh] = __expf(v0[hh] - m[hh]);
            s[hh]  = w0[hh];
        }
    }
    for (int e = start + 32 + lane; e < end; e += 32) {
        int sn = src[e];
#pragma unroll
        for (int hh = 0; hh < H; hh++)
            s[hh] += __expf(leaky02(el[sn * H + hh] + er_d[hh]) - m[hh]);
    }
#pragma unroll
    for (int hh = 0; hh < H; hh++)
#pragma unroll
        for (int o = 16; o; o >>= 1)
            s[hh] += __shfl_xor_sync(0xffffffffu, s[hh], o);
    float inv[H];
#pragma unroll
    for (int hh = 0; hh < H; hh++)
        inv[hh] = (s[hh] > 0.f) ? 1.0f / s[hh] : 0.f;

    if (start + lane < end) {
        int e = start + lane;
#pragma unroll
        for (int hh = 0; hh < H; hh++)
            alpha[(size_t)e * H + hh] = w0[hh] * inv[hh];
    }
    for (int e = start + 32 + lane; e < end; e += 32) {
        int sn = src[e];
#pragma unroll
        for (int hh = 0; hh < H; hh++)
            alpha[(size_t)e * H + hh] =
                __expf(leaky02(el[sn * H + hh] + er_d[hh]) - m[hh]) * inv[hh];
    }
}

// ---------------------------------------------------------------------------
// gat_gather: warp per dst. Pure weighted feature gather, unrolled by 2.
// ---------------------------------------------------------------------------
template <int H, int D, int STRIDE, bool RELU, bool TF32OUT>
__global__ __launch_bounds__(256) void gat_gather(
    const float* __restrict__ h, const float* __restrict__ alpha,
    const int* __restrict__ src, const int* __restrict__ rp,
    float* __restrict__ out, int n_dst)
{
    constexpr int HD  = H * D;
    constexpr int HD4 = HD / 4;
    constexpr int NJ  = (HD4 + 31) / 32;

    const int gw = (blockIdx.x * blockDim.x + threadIdx.x) >> 5;
    if (gw >= n_dst) return;
    const int lane = threadIdx.x & 31;
    const int d = gw;
    const int start = rp[d];
    const int end   = rp[d + 1];

    int headj[NJ];
#pragma unroll
    for (int jj = 0; jj < NJ; jj++) {
        int j = lane + jj * 32;
        int hh = (j * 4) / D;
        headj[jj] = hh < H ? hh : H - 1;
    }

    float4 facc[NJ];
#pragma unroll
    for (int jj = 0; jj < NJ; jj++) facc[jj] = make_float4(0.f, 0.f, 0.f, 0.f);

    int e = start;
    for (; e + 2 <= end; e += 2) {
        const int sn0 = __ldg(&src[e]);
        const int sn1 = __ldg(&src[e + 1]);
        float a0[NJ], a1[NJ];
#pragma unroll
        for (int jj = 0; jj < NJ; jj++) {
            a0[jj] = __ldg(&alpha[(size_t)e * H + headj[jj]]);
            a1[jj] = __ldg(&alpha[(size_t)(e + 1) * H + headj[jj]]);
        }
        const float4* hp0 = (const float4*)(h + (size_t)sn0 * STRIDE);
        const float4* hp1 = (const float4*)(h + (size_t)sn1 * STRIDE);
#pragma unroll
        for (int jj = 0; jj < NJ; jj++) {
            int j = lane + jj * 32;
            if (j < HD4) {
                float4 v0 = hp0[j];
                float4 v1 = hp1[j];
                facc[jj].x = fmaf(v0.x, a0[jj], facc[jj].x);
                facc[jj].y = fmaf(v0.y, a0[jj], facc[jj].y);
                facc[jj].z = fmaf(v0.z, a0[jj], facc[jj].z);
                facc[jj].w = fmaf(v0.w, a0[jj], facc[jj].w);
                facc[jj].x = fmaf(v1.x, a1[jj], facc[jj].x);
                facc[jj].y = fmaf(v1.y, a1[jj], facc[jj].y);
                facc[jj].z = fmaf(v1.z, a1[jj], facc[jj].z);
                facc[jj].w = fmaf(v1.w, a1[jj], facc[jj].w);
            }
        }
    }
    if (e < end) {
        const int sn0 = __ldg(&src[e]);
        const float4* hp0 = (const float4*)(h + (size_t)sn0 * STRIDE);
#pragma unroll
        for (int jj = 0; jj < NJ; jj++) {
            int j = lane + jj * 32;
            if (j < HD4) {
                float a = __ldg(&alpha[(size_t)e * H + headj[jj]]);
                float4 v = hp0[j];
                facc[jj].x = fmaf(v.x, a, facc[jj].x);
                facc[jj].y = fmaf(v.y, a, facc[jj].y);
                facc[jj].z = fmaf(v.z, a, facc[jj].z);
                facc[jj].w = fmaf(v.w, a, facc[jj].w);
            }
        }
    }

#pragma unroll
    for (int jj = 0; jj < NJ; jj++) {
        int j = lane + jj * 32;
        if (j < HD4) {
            float4 r = facc[jj];
            if (RELU) {
                r.x = fmaxf(r.x, 0.f); r.y = fmaxf(r.y, 0.f);
                r.z = fmaxf(r.z, 0.f); r.w = fmaxf(r.w, 0.f);
            }
            if (TF32OUT) {
                r.x = wmma::__float_to_tf32(r.x);
                r.y = wmma::__float_to_tf32(r.y);
                r.z = wmma::__float_to_tf32(r.z);
                r.w = wmma::__float_to_tf32(r.w);
            }
            ((float4*)(out + (size_t)d * HD))[j] = r;
        }
    }
}

// ---------------------------------------------------------------------------
// Launch
// ---------------------------------------------------------------------------
static inline int ceil_div(int a, int b) { return (a + b - 1) / b; }

extern "C" void kernel_launch(void* const* d_in, const int* in_sizes, int n_in,
                              void* d_out, int out_size)
{
    const float* x    = (const float*)d_in[0];
    const int*   src0 = (const int*)  d_in[1];
    const int*   dst0 = (const int*)  d_in[2];
    const int*   src1 = (const int*)  d_in[3];
    const int*   dst1 = (const int*)  d_in[4];
    const int*   src2 = (const int*)  d_in[5];
    const int*   dst2 = (const int*)  d_in[6];
    const float* W0   = (const float*)d_in[7];
    const float* al0  = (const float*)d_in[8];
    const float* ar0  = (const float*)d_in[9];
    const float* W1   = (const float*)d_in[10];
    const float* al1  = (const float*)d_in[11];
    const float* ar1  = (const float*)d_in[12];
    const float* W2   = (const float*)d_in[13];
    const float* al2  = (const float*)d_in[14];
    const float* ar2  = (const float*)d_in[15];
    float* out = (float*)d_out;

    const int E0 = in_sizes[1];
    const int E1 = in_sizes[3];
    const int E2 = in_sizes[5];

    float *hbuf, *obuf, *el, *er, *alpha, *w0r, *w1r, *w2r;
    int* rp;
    cudaGetSymbolAddress((void**)&hbuf,  g_hbuf);
    cudaGetSymbolAddress((void**)&obuf,  g_obuf);
    cudaGetSymbolAddress((void**)&el,    g_el);
    cudaGetSymbolAddress((void**)&er,    g_er);
    cudaGetSymbolAddress((void**)&alpha, g_alpha);
    cudaGetSymbolAddress((void**)&w0r,   g_W0r);
    cudaGetSymbolAddress((void**)&w1r,   g_W1r);
    cudaGetSymbolAddress((void**)&w2r,   g_W2r);
    cudaGetSymbolAddress((void**)&rp,    g_rowptr);

    round_w_kernel<<<ceil_div(FIN * FMID, 256), 256>>>(W0, W1, W2, w0r, w1r, w2r);

    // ---------------- Layer 0: 200000x256 @ 256x192 ----------------
    {
        dim3 grid(FMID / 64, ceil_div(NODES0, 128));
        gemm_tf32_pipe<true><<<grid, 256>>>(x, w0r, hbuf, NODES0, FMID, FIN, FMID);

        int warps = NODES0 * NHEAD;
        elr_kernel<<<ceil_div(warps * 32, 256), 256>>>(hbuf, al0, ar0, el, er,
                                                       NODES0, NHEAD, DH, FMID);
        rowptr_fast<<<ceil_div(E0, 256), 256>>>(dst0, E0, NODES1, rp);
        gat_softmax<NHEAD><<<ceil_div(NODES1, 8), 256>>>(el, er, src0, rp, alpha, NODES1);
        gat_gather<NHEAD, DH, FMID, true, true><<<ceil_div(NODES1, 8), 256>>>(
            hbuf, alpha, src0, rp, obuf, NODES1);
    }

    // ---------------- Layer 1: 100000x192 @ 192x192 ----------------
    {
        dim3 grid(FMID / 64, ceil_div(NODES1, 128));
        gemm_tf32_pipe<false><<<grid, 256>>>(obuf, w1r, hbuf, NODES1, FMID, FMID, FMID);

        int warps = NODES1 * NHEAD;
        elr_kernel<<<ceil_div(warps * 32, 256), 256>>>(hbuf, al1, ar1, el, er,
                                                       NODES1, NHEAD, DH, FMID);
        rowptr_fast<<<ceil_div(E1, 256), 256>>>(dst1, E1, NODES2, rp);
        gat_softmax<NHEAD><<<ceil_div(NODES2, 8), 256>>>(el, er, src1, rp, alpha, NODES2);
        gat_gather<NHEAD, DH, FMID, true, true><<<ceil_div(NODES2, 8), 256>>>(
            hbuf, alpha, src1, rp, obuf, NODES2);
    }

    // ---------------- Layer 2: 50000x192 @ 192x40 (padded ldc=48) -------
    {
        dim3 grid(1, ceil_div(NODES2, 128));
        gemm_tf32_pipe<false><<<grid, 256>>>(obuf, w2r, hbuf, NODES2, COUT, FMID, COUT_PAD);

        int warps = NODES2 * 1;
        elr_kernel<<<ceil_div(warps * 32, 256), 256>>>(hbuf, al2, ar2, el, er,
                                                       NODES2, 1, COUT, COUT_PAD);
        rowptr_fast<<<ceil_div(E2, 256), 256>>>(dst2, E2, NODES3, rp);
        gat_softmax<1><<<ceil_div(NODES3, 8), 256>>>(el, er, src2, rp, alpha, NODES3);
        gat_gather<1, COUT, COUT_PAD, false, false><<<ceil_div(NODES3, 8), 256>>>(
            hbuf, alpha, src2, rp, out, NODES3);
    }
}

// round 9
// speedup vs baseline: 1.1109x; 1.0504x over previous
#include <cuda_runtime.h>
#include <cstdint>
#include <mma.h>
#include <math.h>

using namespace nvcuda;

// ---------------------------------------------------------------------------
// Problem constants
// ---------------------------------------------------------------------------
#define NODES0 200000
#define NODES1 100000
#define NODES2 50000
#define NODES3 25000
#define FIN    256
#define DH     64
#define NHEAD  3
#define COUT   40
#define FMID   (NHEAD * DH)   // 192
#define COUT_PAD 48
#define EDGE_MAX 1000000

// ---------------------------------------------------------------------------
// Static device scratch
// ---------------------------------------------------------------------------
__device__ __align__(128) float g_hbuf[(size_t)NODES0 * FMID];
__device__ __align__(128) float g_obuf[(size_t)NODES1 * FMID];
__device__ __align__(128) float g_el[(size_t)NODES0 * NHEAD];
__device__ __align__(128) float g_er[(size_t)NODES0 * NHEAD];
__device__ __align__(128) float g_alpha[(size_t)EDGE_MAX * NHEAD];
__device__ __align__(128) float g_W0r[FIN * FMID];
__device__ __align__(128) float g_W1r[FMID * FMID];
__device__ __align__(128) float g_W2r[FMID * COUT];
__device__ int g_rowptr[NODES1 + 1];

// ---------------------------------------------------------------------------
// cp.async helpers
// ---------------------------------------------------------------------------
__device__ __forceinline__ unsigned int smem_u32(const void* p) {
    return (unsigned int)__cvta_generic_to_shared(p);
}
__device__ __forceinline__ void cp16(unsigned int d, const void* s) {
    asm volatile("cp.async.cg.shared.global [%0], [%1], 16;" :: "r"(d), "l"(s));
}
#define CP_COMMIT() asm volatile("cp.async.commit_group;")
#define CP_WAIT0()  asm volatile("cp.async.wait_group 0;")

// ---------------------------------------------------------------------------
// Pre-round weight matrices to tf32-representable fp32 (RN), once per call.
// ---------------------------------------------------------------------------
__global__ void round_w_kernel(const float* __restrict__ W0,
                               const float* __restrict__ W1,
                               const float* __restrict__ W2,
                               float* __restrict__ W0r,
                               float* __restrict__ W1r,
                               float* __restrict__ W2r)
{
    int i = blockIdx.x * blockDim.x + threadIdx.x;
    if (i < FIN * FMID)  W0r[i] = wmma::__float_to_tf32(W0[i]);
    if (i < FMID * FMID) W1r[i] = wmma::__float_to_tf32(W1[i]);
    if (i < FMID * COUT) W2r[i] = wmma::__float_to_tf32(W2[i]);
}

// ---------------------------------------------------------------------------
// TF32 wmma GEMM, FULL-N tile: BN_ covers the whole output width, so A is
// streamed exactly ONCE (old BN=64 design re-read A for each of N/64 column
// blocks). 2-stage cp.async double buffer (fits 48KB static smem).
// BM=128, BK=16, 256 threads. Warp layout WM_ x WN_; warp tile
// (128/WM_) x (BN_/WN_) of m16n16k8 fragments.
//   L0/L1: BN_=192, WM_=4, WN_=2 -> warp tile 32x96 (2x6 frags, 12 MMA/chunk)
//   L2:    BN_=48,  WM_=8, WN_=1 -> warp tile 16x48 (1x3 frags)
// ---------------------------------------------------------------------------
template <int BN_, int WM_, int WN_, bool CONVA>
__global__ __launch_bounds__(256) void gemm_fullN(
    const float* __restrict__ A, const float* __restrict__ B,
    float* __restrict__ C, int M, int N, int K, int ldc)
{
    constexpr int BM = 128, BK = 16;
    constexpr int LDA = BK + 4;             // 20
    constexpr int LDB = BN_ + 4;            // 196 / 52
    constexpr int WTM = BM / WM_;           // 32 / 16
    constexpr int WTN = BN_ / WN_;          // 96 / 48
    constexpr int MF  = WTM / 16;           // 2 / 1
    constexpr int NF  = WTN / 16;           // 6 / 3
    constexpr int BE4 = BK * BN_ / 4;       // B float4 count: 768 / 192

    __shared__ float As[2][BM * LDA];
    __shared__ float Bs[2][BK * LDB];

    const int tid  = threadIdx.x;
    const int warp = tid >> 5;
    const int wm   = warp / WN_;
    const int wn   = warp % WN_;
    const int brow = blockIdx.x * BM;
    const int T    = K / BK;

    wmma::fragment<wmma::accumulator, 16, 16, 8, float> acc[MF][NF];
#pragma unroll
    for (int i = 0; i < MF; i++)
#pragma unroll
        for (int j = 0; j < NF; j++) wmma::fill_fragment(acc[i][j], 0.0f);

#define PREFETCH(t, st)                                                        \
    do {                                                                       \
        int k0 = (t) * BK;                                                     \
        _Pragma("unroll")                                                      \
        for (int i = 0; i < 2; i++) {                                          \
            int idx = tid + i * 256;                                           \
            int r   = idx >> 2;                                                \
            int c4  = idx & 3;                                                 \
            int grow = brow + r;                                               \
            if (grow >= M) grow = M - 1;                                       \
            cp16(smem_u32(&As[st][r * LDA + c4 * 4]),                          \
                 &A[(size_t)grow * K + k0 + c4 * 4]);                          \
        }                                                                      \
        _Pragma("unroll")                                                      \
        for (int i = 0; i < (BE4 + 255) / 256; i++) {                          \
            int idx = tid + i * 256;                                           \
            if (idx < BE4) {                                                   \
                int r  = idx / (BN_ / 4);                                      \
                int c4 = idx % (BN_ / 4);                                      \
                int gc = c4 * 4;                                               \
                if (gc + 4 > N) gc = N - 4; /* dup data into pad cols */       \
                cp16(smem_u32(&Bs[st][r * LDB + c4 * 4]),                      \
                     &B[(size_t)(k0 + r) * N + gc]);                           \
            }                                                                  \
        }                                                                      \
        CP_COMMIT();                                                           \
    } while (0)

    PREFETCH(0, 0);

    for (int t = 0; t < T; t++) {
        CP_WAIT0();          // tile t resident
        __syncthreads();     // all warps see it; prev compute done
        if (t + 1 < T)
            PREFETCH(t + 1, (t + 1) & 1);   // overlaps with compute below
        const int st = t & 1;
#pragma unroll
        for (int kk = 0; kk < BK; kk += 8) {
            wmma::fragment<wmma::matrix_a, 16, 16, 8, wmma::precision::tf32, wmma::row_major> a[MF];
            wmma::fragment<wmma::matrix_b, 16, 16, 8, wmma::precision::tf32, wmma::row_major> b[NF];
#pragma unroll
            for (int i = 0; i < MF; i++) {
                wmma::load_matrix_sync(a[i], &As[st][(wm * WTM + i * 16) * LDA + kk], LDA);
                if (CONVA) {
#pragma unroll
                    for (int e = 0; e < a[i].num_elements; e++)
                        a[i].x[e] = wmma::__float_to_tf32(a[i].x[e]);
                }
            }
#pragma unroll
            for (int j = 0; j < NF; j++)
                wmma::load_matrix_sync(b[j], &Bs[st][kk * LDB + wn * WTN + j * 16], LDB);
#pragma unroll
            for (int i = 0; i < MF; i++)
#pragma unroll
                for (int j = 0; j < NF; j++)
                    wmma::mma_sync(acc[i][j], a[i], b[j], acc[i][j]);
        }
        __syncthreads();     // compute done before next overwrite of st
    }
#undef PREFETCH

#pragma unroll
    for (int i = 0; i < MF; i++) {
        int row0 = brow + wm * WTM + i * 16;
        if (row0 + 16 > M) continue;
#pragma unroll
        for (int j = 0; j < NF; j++) {
            int col0 = wn * WTN + j * 16;
            if (col0 + 16 > ldc) continue;
            wmma::store_matrix_sync(&C[(size_t)row0 * ldc + col0], acc[i][j], ldc,
                                    wmma::mem_row_major);
        }
    }
}

// ---------------------------------------------------------------------------
// Per-node attention logits (R6-proven scalar form; full-warp active).
// ---------------------------------------------------------------------------
__global__ void elr_kernel(const float* __restrict__ h,
                           const float* __restrict__ al,
                           const float* __restrict__ ar,
                           float* __restrict__ el, float* __restrict__ er,
                           int Nn, int H, int D, int stride)
{
    int gw   = (blockIdx.x * blockDim.x + threadIdx.x) >> 5;
    int lane = threadIdx.x & 31;
    if (gw >= Nn * H) return;
    int n = gw / H, head = gw % H;
    const float* hp  = h  + (size_t)n * stride + head * D;
    const float* alp = al + head * D;
    const float* arp = ar + head * D;
    float sl = 0.f, sr = 0.f;
    for (int d = lane; d < D; d += 32) {
        float v = hp[d];
        sl = fmaf(v, alp[d], sl);
        sr = fmaf(v, arp[d], sr);
    }
#pragma unroll
    for (int o = 16; o; o >>= 1) {
        sl += __shfl_xor_sync(0xffffffffu, sl, o);
        sr += __shfl_xor_sync(0xffffffffu, sr, o);
    }
    if (lane == 0) {
        el[n * H + head] = sl;
        er[n * H + head] = sr;
    }
}

// ---------------------------------------------------------------------------
// row_ptr from sorted dst — edge-diff scatter (thread per edge; proven win).
// ---------------------------------------------------------------------------
__global__ void rowptr_fast(const int* __restrict__ dst, int E, int n_dst,
                            int* __restrict__ rp)
{
    int e = blockIdx.x * blockDim.x + threadIdx.x;
    if (e >= E) return;
    int d1 = dst[e];
    int d0 = (e == 0) ? -1 : dst[e - 1];
    for (int d = d0 + 1; d <= d1; d++) rp[d] = e;
    if (e == E - 1)
        for (int d = d1 + 1; d <= n_dst; d++) rp[d] = E;
}

// ---------------------------------------------------------------------------
// gat_softmax: warp per dst. Max-shifted softmax; writes normalized alpha.
// ---------------------------------------------------------------------------
__device__ __forceinline__ float leaky02(float v) {
    return v > 0.f ? v : 0.2f * v;
}

template <int H>
__global__ __launch_bounds__(256) void gat_softmax(
    const float* __restrict__ el, const float* __restrict__ er,
    const int* __restrict__ src, const int* __restrict__ rp,
    float* __restrict__ alpha, int n_dst)
{
    const int gw = (blockIdx.x * blockDim.x + threadIdx.x) >> 5;
    if (gw >= n_dst) return;
    const int lane = threadIdx.x & 31;
    const int d = gw;
    const int start = rp[d];
    const int end   = rp[d + 1];

    float er_d[H];
#pragma unroll
    for (int hh = 0; hh < H; hh++) er_d[hh] = er[d * H + hh];

    float v0[H], m[H];
#pragma unroll
    for (int hh = 0; hh < H; hh++) { v0[hh] = 0.f; m[hh] = -INFINITY; }
    {
        int e = start + lane;
        if (e < end) {
            int sn = src[e];
#pragma unroll
            for (int hh = 0; hh < H; hh++) {
                v0[hh] = leaky02(el[sn * H + hh] + er_d[hh]);
                m[hh]  = v0[hh];
            }
        }
    }
    for (int e = start + 32 + lane; e < end; e += 32) {
        int sn = src[e];
#pragma unroll
        for (int hh = 0; hh < H; hh++)
            m[hh] = fmaxf(m[hh], leaky02(el[sn * H + hh] + er_d[hh]));
    }
#pragma unroll
    for (int hh = 0; hh < H; hh++)
#pragma unroll
        for (int o = 16; o; o >>= 1)
            m[hh] = fmaxf(m[hh], __shfl_xor_sync(0xffffffffu, m[hh], o));

    float w0[H], s[H];
#pragma unroll
    for (int hh = 0; hh < H; hh++) { s[hh] = 0.f; w0[hh] = 0.f; }
    if (start + lane < end) {
#pragma unroll
        for (int hh = 0; hh < H; hh++) {
            w0[hh] = __expf(v0[hh] - m[hh]);
            s[hh]  = w0[hh];
        }
    }
    for (int e = start + 32 + lane; e < end; e += 32) {
        int sn = src[e];
#pragma unroll
        for (int hh = 0; hh < H; hh++)
            s[hh] += __expf(leaky02(el[sn * H + hh] + er_d[hh]) - m[hh]);
    }
#pragma unroll
    for (int hh = 0; hh < H; hh++)
#pragma unroll
        for (int o = 16; o; o >>= 1)
            s[hh] += __shfl_xor_sync(0xffffffffu, s[hh], o);
    float inv[H];
#pragma unroll
    for (int hh = 0; hh < H; hh++)
        inv[hh] = (s[hh] > 0.f) ? 1.0f / s[hh] : 0.f;

    if (start + lane < end) {
        int e = start + lane;
#pragma unroll
        for (int hh = 0; hh < H; hh++)
            alpha[(size_t)e * H + hh] = w0[hh] * inv[hh];
    }
    for (int e = start + 32 + lane; e < end; e += 32) {
        int sn = src[e];
#pragma unroll
        for (int hh = 0; hh < H; hh++)
            alpha[(size_t)e * H + hh] =
                __expf(leaky02(el[sn * H + hh] + er_d[hh]) - m[hh]) * inv[hh];
    }
}

// ---------------------------------------------------------------------------
// gat_gather: warp per dst. Pure weighted feature gather, unrolled by 2.
// ---------------------------------------------------------------------------
template <int H, int D, int STRIDE, bool RELU, bool TF32OUT>
__global__ __launch_bounds__(256) void gat_gather(
    const float* __restrict__ h, const float* __restrict__ alpha,
    const int* __restrict__ src, const int* __restrict__ rp,
    float* __restrict__ out, int n_dst)
{
    constexpr int HD  = H * D;
    constexpr int HD4 = HD / 4;
    constexpr int NJ  = (HD4 + 31) / 32;

    const int gw = (blockIdx.x * blockDim.x + threadIdx.x) >> 5;
    if (gw >= n_dst) return;
    const int lane = threadIdx.x & 31;
    const int d = gw;
    const int start = rp[d];
    const int end   = rp[d + 1];

    int headj[NJ];
#pragma unroll
    for (int jj = 0; jj < NJ; jj++) {
        int j = lane + jj * 32;
        int hh = (j * 4) / D;
        headj[jj] = hh < H ? hh : H - 1;
    }

    float4 facc[NJ];
#pragma unroll
    for (int jj = 0; jj < NJ; jj++) facc[jj] = make_float4(0.f, 0.f, 0.f, 0.f);

    int e = start;
    for (; e + 2 <= end; e += 2) {
        const int sn0 = __ldg(&src[e]);
        const int sn1 = __ldg(&src[e + 1]);
        float a0[NJ], a1[NJ];
#pragma unroll
        for (int jj = 0; jj < NJ; jj++) {
            a0[jj] = __ldg(&alpha[(size_t)e * H + headj[jj]]);
            a1[jj] = __ldg(&alpha[(size_t)(e + 1) * H + headj[jj]]);
        }
        const float4* hp0 = (const float4*)(h + (size_t)sn0 * STRIDE);
        const float4* hp1 = (const float4*)(h + (size_t)sn1 * STRIDE);
#pragma unroll
        for (int jj = 0; jj < NJ; jj++) {
            int j = lane + jj * 32;
            if (j < HD4) {
                float4 v0 = hp0[j];
                float4 v1 = hp1[j];
                facc[jj].x = fmaf(v0.x, a0[jj], facc[jj].x);
                facc[jj].y = fmaf(v0.y, a0[jj], facc[jj].y);
                facc[jj].z = fmaf(v0.z, a0[jj], facc[jj].z);
                facc[jj].w = fmaf(v0.w, a0[jj], facc[jj].w);
                facc[jj].x = fmaf(v1.x, a1[jj], facc[jj].x);
                facc[jj].y = fmaf(v1.y, a1[jj], facc[jj].y);
                facc[jj].z = fmaf(v1.z, a1[jj], facc[jj].z);
                facc[jj].w = fmaf(v1.w, a1[jj], facc[jj].w);
            }
        }
    }
    if (e < end) {
        const int sn0 = __ldg(&src[e]);
        const float4* hp0 = (const float4*)(h + (size_t)sn0 * STRIDE);
#pragma unroll
        for (int jj = 0; jj < NJ; jj++) {
            int j = lane + jj * 32;
            if (j < HD4) {
                float a = __ldg(&alpha[(size_t)e * H + headj[jj]]);
                float4 v = hp0[j];
                facc[jj].x = fmaf(v.x, a, facc[jj].x);
                facc[jj].y = fmaf(v.y, a, facc[jj].y);
                facc[jj].z = fmaf(v.z, a, facc[jj].z);
                facc[jj].w = fmaf(v.w, a, facc[jj].w);
            }
        }
    }

#pragma unroll
    for (int jj = 0; jj < NJ; jj++) {
        int j = lane + jj * 32;
        if (j < HD4) {
            float4 r = facc[jj];
            if (RELU) {
                r.x = fmaxf(r.x, 0.f); r.y = fmaxf(r.y, 0.f);
                r.z = fmaxf(r.z, 0.f); r.w = fmaxf(r.w, 0.f);
            }
            if (TF32OUT) {
                r.x = wmma::__float_to_tf32(r.x);
                r.y = wmma::__float_to_tf32(r.y);
                r.z = wmma::__float_to_tf32(r.z);
                r.w = wmma::__float_to_tf32(r.w);
            }
            ((float4*)(out + (size_t)d * HD))[j] = r;
        }
    }
}

// ---------------------------------------------------------------------------
// Launch
// ---------------------------------------------------------------------------
static inline int ceil_div(int a, int b) { return (a + b - 1) / b; }

extern "C" void kernel_launch(void* const* d_in, const int* in_sizes, int n_in,
                              void* d_out, int out_size)
{
    const float* x    = (const float*)d_in[0];
    const int*   src0 = (const int*)  d_in[1];
    const int*   dst0 = (const int*)  d_in[2];
    const int*   src1 = (const int*)  d_in[3];
    const int*   dst1 = (const int*)  d_in[4];
    const int*   src2 = (const int*)  d_in[5];
    const int*   dst2 = (const int*)  d_in[6];
    const float* W0   = (const float*)d_in[7];
    const float* al0  = (const float*)d_in[8];
    const float* ar0  = (const float*)d_in[9];
    const float* W1   = (const float*)d_in[10];
    const float* al1  = (const float*)d_in[11];
    const float* ar1  = (const float*)d_in[12];
    const float* W2   = (const float*)d_in[13];
    const float* al2  = (const float*)d_in[14];
    const float* ar2  = (const float*)d_in[15];
    float* out = (float*)d_out;

    const int E0 = in_sizes[1];
    const int E1 = in_sizes[3];
    const int E2 = in_sizes[5];

    float *hbuf, *obuf, *el, *er, *alpha, *w0r, *w1r, *w2r;
    int* rp;
    cudaGetSymbolAddress((void**)&hbuf,  g_hbuf);
    cudaGetSymbolAddress((void**)&obuf,  g_obuf);
    cudaGetSymbolAddress((void**)&el,    g_el);
    cudaGetSymbolAddress((void**)&er,    g_er);
    cudaGetSymbolAddress((void**)&alpha, g_alpha);
    cudaGetSymbolAddress((void**)&w0r,   g_W0r);
    cudaGetSymbolAddress((void**)&w1r,   g_W1r);
    cudaGetSymbolAddress((void**)&w2r,   g_W2r);
    cudaGetSymbolAddress((void**)&rp,    g_rowptr);

    round_w_kernel<<<ceil_div(FIN * FMID, 256), 256>>>(W0, W1, W2, w0r, w1r, w2r);

    // ---------------- Layer 0: 200000x256 @ 256x192 ----------------
    {
        gemm_fullN<FMID, 4, 2, true><<<ceil_div(NODES0, 128), 256>>>(
            x, w0r, hbuf, NODES0, FMID, FIN, FMID);

        int warps = NODES0 * NHEAD;
        elr_kernel<<<ceil_div(warps * 32, 256), 256>>>(hbuf, al0, ar0, el, er,
                                                       NODES0, NHEAD, DH, FMID);
        rowptr_fast<<<ceil_div(E0, 256), 256>>>(dst0, E0, NODES1, rp);
        gat_softmax<NHEAD><<<ceil_div(NODES1, 8), 256>>>(el, er, src0, rp, alpha, NODES1);
        gat_gather<NHEAD, DH, FMID, true, true><<<ceil_div(NODES1, 8), 256>>>(
            hbuf, alpha, src0, rp, obuf, NODES1);
    }

    // ---------------- Layer 1: 100000x192 @ 192x192 ----------------
    {
        gemm_fullN<FMID, 4, 2, false><<<ceil_div(NODES1, 128), 256>>>(
            obuf, w1r, hbuf, NODES1, FMID, FMID, FMID);

        int warps = NODES1 * NHEAD;
        elr_kernel<<<ceil_div(warps * 32, 256), 256>>>(hbuf, al1, ar1, el, er,
                                                       NODES1, NHEAD, DH, FMID);
        rowptr_fast<<<ceil_div(E1, 256), 256>>>(dst1, E1, NODES2, rp);
        gat_softmax<NHEAD><<<ceil_div(NODES2, 8), 256>>>(el, er, src1, rp, alpha, NODES2);
        gat_gather<NHEAD, DH, FMID, true, true><<<ceil_div(NODES2, 8), 256>>>(
            hbuf, alpha, src1, rp, obuf, NODES2);
    }

    // ---------------- Layer 2: 50000x192 @ 192x40 (padded ldc=48) -------
    {
        gemm_fullN<COUT_PAD, 8, 1, false><<<ceil_div(NODES2, 128), 256>>>(
            obuf, w2r, hbuf, NODES2, COUT, FMID, COUT_PAD);

        int warps = NODES2 * 1;
        elr_kernel<<<ceil_div(warps * 32, 256), 256>>>(hbuf, al2, ar2, el, er,
                                                       NODES2, 1, COUT, COUT_PAD);
        rowptr_fast<<<ceil_div(E2, 256), 256>>>(dst2, E2, NODES3, rp);
        gat_softmax<1><<<ceil_div(NODES3, 8), 256>>>(el, er, src2, rp, alpha, NODES3);
        gat_gather<1, COUT, COUT_PAD, false, false><<<ceil_div(NODES3, 8), 256>>>(
            hbuf, alpha, src2, rp, out, NODES3);
    }
}

// round 10
// speedup vs baseline: 1.2260x; 1.1037x over previous
#include <cuda_runtime.h>
#include <cstdint>
#include <mma.h>
#include <math.h>

using namespace nvcuda;

// ---------------------------------------------------------------------------
// Problem constants
// ---------------------------------------------------------------------------
#define NODES0 200000
#define NODES1 100000
#define NODES2 50000
#define NODES3 25000
#define FIN    256
#define DH     64
#define NHEAD  3
#define COUT   40
#define FMID   (NHEAD * DH)   // 192
#define COUT_PAD 48
#define EDGE_MAX 1000000

// ---------------------------------------------------------------------------
// Static device scratch
// ---------------------------------------------------------------------------
__device__ __align__(128) float g_hbuf[(size_t)NODES0 * FMID];
__device__ __align__(128) float g_obuf[(size_t)NODES1 * FMID];
__device__ __align__(128) float g_el[(size_t)NODES0 * NHEAD];
__device__ __align__(128) float g_er[(size_t)NODES0 * NHEAD];
__device__ __align__(128) float g_alpha[(size_t)EDGE_MAX * NHEAD];
__device__ __align__(128) float g_W0r[FIN * FMID];
__device__ __align__(128) float g_W1r[FMID * FMID];
__device__ __align__(128) float g_W2r[FMID * COUT];
__device__ int g_rowptr[NODES1 + 1];

// ---------------------------------------------------------------------------
// cp.async helpers
// ---------------------------------------------------------------------------
__device__ __forceinline__ unsigned int smem_u32(const void* p) {
    return (unsigned int)__cvta_generic_to_shared(p);
}
__device__ __forceinline__ void cp16(unsigned int d, const void* s) {
    asm volatile("cp.async.cg.shared.global [%0], [%1], 16;" :: "r"(d), "l"(s));
}
#define CP_COMMIT() asm volatile("cp.async.commit_group;")
#define CP_WAIT0()  asm volatile("cp.async.wait_group 0;")

// ---------------------------------------------------------------------------
// Pre-round weight matrices to tf32-representable fp32 (RN), once per call.
// ---------------------------------------------------------------------------
__global__ void round_w_kernel(const float* __restrict__ W0,
                               const float* __restrict__ W1,
                               const float* __restrict__ W2,
                               float* __restrict__ W0r,
                               float* __restrict__ W1r,
                               float* __restrict__ W2r)
{
    int i = blockIdx.x * blockDim.x + threadIdx.x;
    if (i < FIN * FMID)  W0r[i] = wmma::__float_to_tf32(W0[i]);
    if (i < FMID * FMID) W1r[i] = wmma::__float_to_tf32(W1[i]);
    if (i < FMID * COUT) W2r[i] = wmma::__float_to_tf32(W2[i]);
}

// ---------------------------------------------------------------------------
// TF32 wmma GEMM, full-N tile, 2-stage cp.async, FUSED el/er epilogue.
// The epilogue works from accumulator REGISTERS: each warp stages one 16x16
// fragment into a private smem slot, dots it with smem-cached al/ar, and
// accumulates per-head partials. No global C re-read (the R7 mistake).
// Fragments never straddle head boundaries (16 | 64).
// For WN_=2 (L0/L1, HEADS=3): warp wn=0 owns head0 + half of head1; wn=1
// owns the other half of head1 + head2. head1 is combined via a 1KB smem
// buffer + one __syncthreads.
// ---------------------------------------------------------------------------
template <int BN_, int WM_, int WN_, bool CONVA, int DHEAD, int HEADS>
__global__ __launch_bounds__(256) void gemm_fused(
    const float* __restrict__ A, const float* __restrict__ B,
    float* __restrict__ C, int M, int N, int K, int ldc,
    const float* __restrict__ alv, const float* __restrict__ arv,
    float* __restrict__ el, float* __restrict__ er)
{
    constexpr int BM = 128, BK = 16;
    constexpr int LDA = BK + 4;             // 20
    constexpr int LDB = BN_ + 4;            // 196 / 52
    constexpr int WTM = BM / WM_;           // 32 / 16
    constexpr int WTN = BN_ / WN_;          // 96 / 48
    constexpr int MF  = WTM / 16;           // 2 / 1
    constexpr int NF  = WTN / 16;           // 6 / 3
    constexpr int BE4 = BK * BN_ / 4;
    constexpr int POOL = 2 * BM * LDA + 2 * BK * LDB;

    __shared__ float pool[POOL];
    float* Asp[2] = { pool, pool + BM * LDA };
    float* Bsp[2] = { pool + 2 * BM * LDA, pool + 2 * BM * LDA + BK * LDB };

    const int tid  = threadIdx.x;
    const int warp = tid >> 5;
    const int lane = tid & 31;
    const int wm   = warp / WN_;
    const int wn   = warp % WN_;
    const int brow = blockIdx.x * BM;
    const int T    = K / BK;

    wmma::fragment<wmma::accumulator, 16, 16, 8, float> acc[MF][NF];
#pragma unroll
    for (int i = 0; i < MF; i++)
#pragma unroll
        for (int j = 0; j < NF; j++) wmma::fill_fragment(acc[i][j], 0.0f);

#define PREFETCH(t, st)                                                        \
    do {                                                                       \
        int k0 = (t) * BK;                                                     \
        _Pragma("unroll")                                                      \
        for (int i = 0; i < 2; i++) {                                          \
            int idx = tid + i * 256;                                           \
            int r   = idx >> 2;                                                \
            int c4  = idx & 3;                                                 \
            int grow = brow + r;                                               \
            if (grow >= M) grow = M - 1;                                       \
            cp16(smem_u32(&Asp[st][r * LDA + c4 * 4]),                         \
                 &A[(size_t)grow * K + k0 + c4 * 4]);                          \
        }                                                                      \
        _Pragma("unroll")                                                      \
        for (int i = 0; i < (BE4 + 255) / 256; i++) {                          \
            int idx = tid + i * 256;                                           \
            if (idx < BE4) {                                                   \
                int r  = idx / (BN_ / 4);                                      \
                int c4 = idx % (BN_ / 4);                                      \
                int gc = c4 * 4;                                               \
                if (gc + 4 > N) gc = N - 4;                                    \
                cp16(smem_u32(&Bsp[st][r * LDB + c4 * 4]),                     \
                     &B[(size_t)(k0 + r) * N + gc]);                           \
            }                                                                  \
        }                                                                      \
        CP_COMMIT();                                                           \
    } while (0)

    PREFETCH(0, 0);

    for (int t = 0; t < T; t++) {
        CP_WAIT0();
        __syncthreads();
        if (t + 1 < T)
            PREFETCH(t + 1, (t + 1) & 1);
        const int st = t & 1;
#pragma unroll
        for (int kk = 0; kk < BK; kk += 8) {
            wmma::fragment<wmma::matrix_a, 16, 16, 8, wmma::precision::tf32, wmma::row_major> a[MF];
            wmma::fragment<wmma::matrix_b, 16, 16, 8, wmma::precision::tf32, wmma::row_major> b[NF];
#pragma unroll
            for (int i = 0; i < MF; i++) {
                wmma::load_matrix_sync(a[i], &Asp[st][(wm * WTM + i * 16) * LDA + kk], LDA);
                if (CONVA) {
#pragma unroll
                    for (int e = 0; e < a[i].num_elements; e++)
                        a[i].x[e] = wmma::__float_to_tf32(a[i].x[e]);
                }
            }
#pragma unroll
            for (int j = 0; j < NF; j++)
                wmma::load_matrix_sync(b[j], &Bsp[st][kk * LDB + wn * WTN + j * 16], LDB);
#pragma unroll
            for (int i = 0; i < MF; i++)
#pragma unroll
                for (int j = 0; j < NF; j++)
                    wmma::mma_sync(acc[i][j], a[i], b[j], acc[i][j]);
        }
        __syncthreads();
    }
#undef PREFETCH

    // ---- Epilogue: C store + fused el/er (registers -> smem staging) ----
    // Carve epilogue smem from the (now idle) pool.
    float* stage = pool;                    // 8 warps * 16*20 = 2560
    float* alsm  = pool + 8 * 16 * 20;      // BN_
    float* arsm  = alsm + BN_;              // BN_
    float* bufl  = arsm + BN_;              // BM (shared-head exchange)
    float* bufr  = bufl + BM;               // BM

    for (int i = tid; i < BN_; i += 256) {
        alsm[i] = (i < N) ? alv[i] : 0.f;
        arsm[i] = (i < N) ? arv[i] : 0.f;
    }
    __syncthreads();

    const int row_l = lane & 15;
    const int half  = lane >> 4;
    float* mystage = stage + warp * (16 * 20);

    float hel[MF][HEADS], her[MF][HEADS];
#pragma unroll
    for (int i = 0; i < MF; i++)
#pragma unroll
        for (int h = 0; h < HEADS; h++) { hel[i][h] = 0.f; her[i][h] = 0.f; }

#pragma unroll
    for (int i = 0; i < MF; i++) {
        const int row0 = brow + wm * WTM + i * 16;
#pragma unroll
        for (int j = 0; j < NF; j++) {
            const int col0 = wn * WTN + j * 16;
            if (row0 + 16 <= M && col0 + 16 <= ldc)
                wmma::store_matrix_sync(&C[(size_t)row0 * ldc + col0], acc[i][j],
                                        ldc, wmma::mem_row_major);
            wmma::store_matrix_sync(mystage, acc[i][j], 20, wmma::mem_row_major);
            __syncwarp();
            float sl = 0.f, sr = 0.f;
#pragma unroll
            for (int c = 0; c < 8; c++) {
                float v = mystage[row_l * 20 + half * 8 + c];
                sl = fmaf(v, alsm[col0 + half * 8 + c], sl);
                sr = fmaf(v, arsm[col0 + half * 8 + c], sr);
            }
            __syncwarp();
            const int hd = col0 / DHEAD;   // frag fully inside one head
#pragma unroll
            for (int h = 0; h < HEADS; h++)
                if (hd == h) { hel[i][h] += sl; her[i][h] += sr; }
        }
    }

    // reduce the two column-halves of each row
#pragma unroll
    for (int i = 0; i < MF; i++)
#pragma unroll
        for (int h = 0; h < HEADS; h++) {
            hel[i][h] += __shfl_xor_sync(0xffffffffu, hel[i][h], 16);
            her[i][h] += __shfl_xor_sync(0xffffffffu, her[i][h], 16);
        }

#pragma unroll
    for (int i = 0; i < MF; i++) {
        const int grow = brow + wm * WTM + i * 16 + row_l;
        const bool w = (half == 0) && (grow < M);
        if (WN_ == 1) {
            if (w) {
#pragma unroll
                for (int h = 0; h < HEADS; h++) {
                    el[grow * HEADS + h] = hel[i][h];
                    er[grow * HEADS + h] = her[i][h];
                }
            }
        } else {                           // WN_=2, HEADS=3, DHEAD=64 layout
            if (w && wn == 0) {
                el[grow * HEADS + 0] = hel[i][0];
                er[grow * HEADS + 0] = her[i][0];
                bufl[grow - brow] = hel[i][1];
                bufr[grow - brow] = her[i][1];
            }
        }
    }
    if (WN_ > 1) {
        __syncthreads();
#pragma unroll
        for (int i = 0; i < MF; i++) {
            const int grow = brow + wm * WTM + i * 16 + row_l;
            const bool w = (half == 0) && (grow < M);
            if (w && wn == 1) {
                el[grow * HEADS + 1] = bufl[grow - brow] + hel[i][1];
                er[grow * HEADS + 1] = bufr[grow - brow] + her[i][1];
                el[grow * HEADS + 2] = hel[i][2];
                er[grow * HEADS + 2] = her[i][2];
            }
        }
    }
}

// ---------------------------------------------------------------------------
// row_ptr from sorted dst — edge-diff scatter (thread per edge; proven win).
// ---------------------------------------------------------------------------
__global__ void rowptr_fast(const int* __restrict__ dst, int E, int n_dst,
                            int* __restrict__ rp)
{
    int e = blockIdx.x * blockDim.x + threadIdx.x;
    if (e >= E) return;
    int d1 = dst[e];
    int d0 = (e == 0) ? -1 : dst[e - 1];
    for (int d = d0 + 1; d <= d1; d++) rp[d] = e;
    if (e == E - 1)
        for (int d = d1 + 1; d <= n_dst; d++) rp[d] = E;
}

// ---------------------------------------------------------------------------
// gat_softmax: warp per dst. Max-shifted softmax; writes normalized alpha.
// ---------------------------------------------------------------------------
__device__ __forceinline__ float leaky02(float v) {
    return v > 0.f ? v : 0.2f * v;
}

template <int H>
__global__ __launch_bounds__(256) void gat_softmax(
    const float* __restrict__ el, const float* __restrict__ er,
    const int* __restrict__ src, const int* __restrict__ rp,
    float* __restrict__ alpha, int n_dst)
{
    const int gw = (blockIdx.x * blockDim.x + threadIdx.x) >> 5;
    if (gw >= n_dst) return;
    const int lane = threadIdx.x & 31;
    const int d = gw;
    const int start = rp[d];
    const int end   = rp[d + 1];

    float er_d[H];
#pragma unroll
    for (int hh = 0; hh < H; hh++) er_d[hh] = er[d * H + hh];

    float v0[H], m[H];
#pragma unroll
    for (int hh = 0; hh < H; hh++) { v0[hh] = 0.f; m[hh] = -INFINITY; }
    {
        int e = start + lane;
        if (e < end) {
            int sn = src[e];
#pragma unroll
            for (int hh = 0; hh < H; hh++) {
                v0[hh] = leaky02(el[sn * H + hh] + er_d[hh]);
                m[hh]  = v0[hh];
            }
        }
    }
    for (int e = start + 32 + lane; e < end; e += 32) {
        int sn = src[e];
#pragma unroll
        for (int hh = 0; hh < H; hh++)
            m[hh] = fmaxf(m[hh], leaky02(el[sn * H + hh] + er_d[hh]));
    }
#pragma unroll
    for (int hh = 0; hh < H; hh++)
#pragma unroll
        for (int o = 16; o; o >>= 1)
            m[hh] = fmaxf(m[hh], __shfl_xor_sync(0xffffffffu, m[hh], o));

    float w0[H], s[H];
#pragma unroll
    for (int hh = 0; hh < H; hh++) { s[hh] = 0.f; w0[hh] = 0.f; }
    if (start + lane < end) {
#pragma unroll
        for (int hh = 0; hh < H; hh++) {
            w0[hh] = __expf(v0[hh] - m[hh]);
            s[hh]  = w0[hh];
        }
    }
    for (int e = start + 32 + lane; e < end; e += 32) {
        int sn = src[e];
#pragma unroll
        for (int hh = 0; hh < H; hh++)
            s[hh] += __expf(leaky02(el[sn * H + hh] + er_d[hh]) - m[hh]);
    }
#pragma unroll
    for (int hh = 0; hh < H; hh++)
#pragma unroll
        for (int o = 16; o; o >>= 1)
            s[hh] += __shfl_xor_sync(0xffffffffu, s[hh], o);
    float inv[H];
#pragma unroll
    for (int hh = 0; hh < H; hh++)
        inv[hh] = (s[hh] > 0.f) ? 1.0f / s[hh] : 0.f;

    if (start + lane < end) {
        int e = start + lane;
#pragma unroll
        for (int hh = 0; hh < H; hh++)
            alpha[(size_t)e * H + hh] = w0[hh] * inv[hh];
    }
    for (int e = start + 32 + lane; e < end; e += 32) {
        int sn = src[e];
#pragma unroll
        for (int hh = 0; hh < H; hh++)
            alpha[(size_t)e * H + hh] =
                __expf(leaky02(el[sn * H + hh] + er_d[hh]) - m[hh]) * inv[hh];
    }
}

// ---------------------------------------------------------------------------
// gat_gather: warp per dst. Pure weighted feature gather, unrolled by 2.
// ---------------------------------------------------------------------------
template <int H, int D, int STRIDE, bool RELU, bool TF32OUT>
__global__ __launch_bounds__(256) void gat_gather(
    const float* __restrict__ h, const float* __restrict__ alpha,
    const int* __restrict__ src, const int* __restrict__ rp,
    float* __restrict__ out, int n_dst)
{
    constexpr int HD  = H * D;
    constexpr int HD4 = HD / 4;
    constexpr int NJ  = (HD4 + 31) / 32;

    const int gw = (blockIdx.x * blockDim.x + threadIdx.x) >> 5;
    if (gw >= n_dst) return;
    const int lane = threadIdx.x & 31;
    const int d = gw;
    const int start = rp[d];
    const int end   = rp[d + 1];

    int headj[NJ];
#pragma unroll
    for (int jj = 0; jj < NJ; jj++) {
        int j = lane + jj * 32;
        int hh = (j * 4) / D;
        headj[jj] = hh < H ? hh : H - 1;
    }

    float4 facc[NJ];
#pragma unroll
    for (int jj = 0; jj < NJ; jj++) facc[jj] = make_float4(0.f, 0.f, 0.f, 0.f);

    int e = start;
    for (; e + 2 <= end; e += 2) {
        const int sn0 = __ldg(&src[e]);
        const int sn1 = __ldg(&src[e + 1]);
        float a0[NJ], a1[NJ];
#pragma unroll
        for (int jj = 0; jj < NJ; jj++) {
            a0[jj] = __ldg(&alpha[(size_t)e * H + headj[jj]]);
            a1[jj] = __ldg(&alpha[(size_t)(e + 1) * H + headj[jj]]);
        }
        const float4* hp0 = (const float4*)(h + (size_t)sn0 * STRIDE);
        const float4* hp1 = (const float4*)(h + (size_t)sn1 * STRIDE);
#pragma unroll
        for (int jj = 0; jj < NJ; jj++) {
            int j = lane + jj * 32;
            if (j < HD4) {
                float4 v0 = hp0[j];
                float4 v1 = hp1[j];
                facc[jj].x = fmaf(v0.x, a0[jj], facc[jj].x);
                facc[jj].y = fmaf(v0.y, a0[jj], facc[jj].y);
                facc[jj].z = fmaf(v0.z, a0[jj], facc[jj].z);
                facc[jj].w = fmaf(v0.w, a0[jj], facc[jj].w);
                facc[jj].x = fmaf(v1.x, a1[jj], facc[jj].x);
                facc[jj].y = fmaf(v1.y, a1[jj], facc[jj].y);
                facc[jj].z = fmaf(v1.z, a1[jj], facc[jj].z);
                facc[jj].w = fmaf(v1.w, a1[jj], facc[jj].w);
            }
        }
    }
    if (e < end) {
        const int sn0 = __ldg(&src[e]);
        const float4* hp0 = (const float4*)(h + (size_t)sn0 * STRIDE);
#pragma unroll
        for (int jj = 0; jj < NJ; jj++) {
            int j = lane + jj * 32;
            if (j < HD4) {
                float a = __ldg(&alpha[(size_t)e * H + headj[jj]]);
                float4 v = hp0[j];
                facc[jj].x = fmaf(v.x, a, facc[jj].x);
                facc[jj].y = fmaf(v.y, a, facc[jj].y);
                facc[jj].z = fmaf(v.z, a, facc[jj].z);
                facc[jj].w = fmaf(v.w, a, facc[jj].w);
            }
        }
    }

#pragma unroll
    for (int jj = 0; jj < NJ; jj++) {
        int j = lane + jj * 32;
        if (j < HD4) {
            float4 r = facc[jj];
            if (RELU) {
                r.x = fmaxf(r.x, 0.f); r.y = fmaxf(r.y, 0.f);
                r.z = fmaxf(r.z, 0.f); r.w = fmaxf(r.w, 0.f);
            }
            if (TF32OUT) {
                r.x = wmma::__float_to_tf32(r.x);
                r.y = wmma::__float_to_tf32(r.y);
                r.z = wmma::__float_to_tf32(r.z);
                r.w = wmma::__float_to_tf32(r.w);
            }
            ((float4*)(out + (size_t)d * HD))[j] = r;
        }
    }
}

// ---------------------------------------------------------------------------
// Launch
// ---------------------------------------------------------------------------
static inline int ceil_div(int a, int b) { return (a + b - 1) / b; }

extern "C" void kernel_launch(void* const* d_in, const int* in_sizes, int n_in,
                              void* d_out, int out_size)
{
    const float* x    = (const float*)d_in[0];
    const int*   src0 = (const int*)  d_in[1];
    const int*   dst0 = (const int*)  d_in[2];
    const int*   src1 = (const int*)  d_in[3];
    const int*   dst1 = (const int*)  d_in[4];
    const int*   src2 = (const int*)  d_in[5];
    const int*   dst2 = (const int*)  d_in[6];
    const float* W0   = (const float*)d_in[7];
    const float* al0  = (const float*)d_in[8];
    const float* ar0  = (const float*)d_in[9];
    const float* W1   = (const float*)d_in[10];
    const float* al1  = (const float*)d_in[11];
    const float* ar1  = (const float*)d_in[12];
    const float* W2   = (const float*)d_in[13];
    const float* al2  = (const float*)d_in[14];
    const float* ar2  = (const float*)d_in[15];
    float* out = (float*)d_out;

    const int E0 = in_sizes[1];
    const int E1 = in_sizes[3];
    const int E2 = in_sizes[5];

    float *hbuf, *obuf, *el, *er, *alpha, *w0r, *w1r, *w2r;
    int* rp;
    cudaGetSymbolAddress((void**)&hbuf,  g_hbuf);
    cudaGetSymbolAddress((void**)&obuf,  g_obuf);
    cudaGetSymbolAddress((void**)&el,    g_el);
    cudaGetSymbolAddress((void**)&er,    g_er);
    cudaGetSymbolAddress((void**)&alpha, g_alpha);
    cudaGetSymbolAddress((void**)&w0r,   g_W0r);
    cudaGetSymbolAddress((void**)&w1r,   g_W1r);
    cudaGetSymbolAddress((void**)&w2r,   g_W2r);
    cudaGetSymbolAddress((void**)&rp,    g_rowptr);

    round_w_kernel<<<ceil_div(FIN * FMID, 256), 256>>>(W0, W1, W2, w0r, w1r, w2r);

    // ---------------- Layer 0: 200000x256 @ 256x192 ----------------
    {
        gemm_fused<FMID, 4, 2, true, DH, NHEAD><<<ceil_div(NODES0, 128), 256>>>(
            x, w0r, hbuf, NODES0, FMID, FIN, FMID, al0, ar0, el, er);
        rowptr_fast<<<ceil_div(E0, 256), 256>>>(dst0, E0, NODES1, rp);
        gat_softmax<NHEAD><<<ceil_div(NODES1, 8), 256>>>(el, er, src0, rp, alpha, NODES1);
        gat_gather<NHEAD, DH, FMID, true, true><<<ceil_div(NODES1, 8), 256>>>(
            hbuf, alpha, src0, rp, obuf, NODES1);
    }

    // ---------------- Layer 1: 100000x192 @ 192x192 ----------------
    {
        gemm_fused<FMID, 4, 2, false, DH, NHEAD><<<ceil_div(NODES1, 128), 256>>>(
            obuf, w1r, hbuf, NODES1, FMID, FMID, FMID, al1, ar1, el, er);
        rowptr_fast<<<ceil_div(E1, 256), 256>>>(dst1, E1, NODES2, rp);
        gat_softmax<NHEAD><<<ceil_div(NODES2, 8), 256>>>(el, er, src1, rp, alpha, NODES2);
        gat_gather<NHEAD, DH, FMID, true, true><<<ceil_div(NODES2, 8), 256>>>(
            hbuf, alpha, src1, rp, obuf, NODES2);
    }

    // ---------------- Layer 2: 50000x192 @ 192x40 (padded ldc=48) -------
    {
        gemm_fused<COUT_PAD, 8, 1, false, 64, 1><<<ceil_div(NODES2, 128), 256>>>(
            obuf, w2r, hbuf, NODES2, COUT, FMID, COUT_PAD, al2, ar2, el, er);
        rowptr_fast<<<ceil_div(E2, 256), 256>>>(dst2, E2, NODES3, rp);
        gat_softmax<1><<<ceil_div(NODES3, 8), 256>>>(el, er, src2, rp, alpha, NODES3);
        gat_gather<1, COUT, COUT_PAD, false, false><<<ceil_div(NODES3, 8), 256>>>(
            hbuf, alpha, src2, rp, out, NODES3);
    }
}